// round 4
// baseline (speedup 1.0000x reference)
#include <cuda_runtime.h>
#include <cstdint>

#define BB   32
#define NN   512
#define DD   256
#define HH   8
#define HDIM 32
#define EE   16384
#define ETOT (EE + NN)

// ---------------- scratch (static device globals; no allocation) -------------
__device__ float g_xwq[BB * NN * DD];
__device__ float g_xwk[BB * NN * DD];
__device__ float g_xwv[BB * NN * DD];
__device__ float g_Q  [BB * NN * DD];
__device__ float g_K  [BB * NN * DD];
__device__ float g_V  [BB * NN * DD];
__device__ float g_att[BB * NN * DD];
__device__ int   g_deg[NN];
__device__ int   g_rowptr[NN + 1];
__device__ int   g_cnt[NN];
__device__ int   g_src [ETOT];
__device__ float g_norm[ETOT];
__device__ int   g_e64;

// ---------------- helpers -----------------------------------------------------
__device__ __forceinline__ uint32_t f2tf32(float f) {
    uint32_t r;
    asm("cvt.rna.tf32.f32 %0, %1;" : "=r"(r) : "f"(f));
    return r;
}

// ---------------- edge dtype detection ---------------------------------------
__global__ void k_detect(const int* __restrict__ e) {
    int nz = 0;
    for (int i = 0; i < 64; i++) nz += (e[2 * i + 1] != 0);
    g_e64 = (nz == 0) ? 1 : 0;
}
__device__ __forceinline__ int edge_at(const int* __restrict__ e, int idx) {
    return g_e64 ? e[2 * idx] : e[idx];
}

// ---------------- graph prep -------------------------------------------------
__global__ void k_init() {
    int t = threadIdx.x;
    if (t < NN) { g_deg[t] = 0; g_cnt[t] = 0; }
}
__global__ void k_deg(const int* __restrict__ edge) {
    int e = blockIdx.x * blockDim.x + threadIdx.x;
    if (e >= ETOT) return;
    int dst = (e < EE) ? edge_at(edge, EE + e) : (e - EE);
    if (dst < 0 || dst >= NN) return;
    atomicAdd(&g_deg[dst], 1);
}
__global__ void k_scan() {
    __shared__ int s[NN];
    int t = threadIdx.x;
    s[t] = g_deg[t];
    __syncthreads();
    for (int off = 1; off < NN; off <<= 1) {
        int v = (t >= off) ? s[t - off] : 0;
        __syncthreads();
        s[t] += v;
        __syncthreads();
    }
    g_rowptr[t + 1] = s[t];
    if (t == 0) g_rowptr[0] = 0;
}
__global__ void k_fill(const int* __restrict__ edge) {
    int e = blockIdx.x * blockDim.x + threadIdx.x;
    if (e >= ETOT) return;
    int s, d;
    if (e < EE) { s = edge_at(edge, e); d = edge_at(edge, EE + e); }
    else        { s = e - EE; d = e - EE; }
    if (s < 0 || s >= NN || d < 0 || d >= NN) return;
    float nm = rsqrtf((float)g_deg[s]) * rsqrtf((float)g_deg[d]);
    int pos = g_rowptr[d] + atomicAdd(&g_cnt[d], 1);
    g_src[pos]  = s;
    g_norm[pos] = nm;
}

// ---------------- tf32 mma.sync GEMM ------------------------------------------
// C[16384,256] = A[16384,256] @ W[256,256] (+bias).
// CTA: BM=128, BN=128, BK=32. 8 warps; warp tile 64x32 (4x4 m16n8k8 frags).
// As stride 36 (frag loads conflict-free), Bs stride 132 (f4-aligned staging).
#define AS_STRIDE 36
#define BS_STRIDE 132

__global__ __launch_bounds__(256) void k_gemm_mma(
    const float* __restrict__ a0p, const float* __restrict__ a1p,
    const float* __restrict__ a2p,
    const float* __restrict__ w0, const float* __restrict__ w1,
    const float* __restrict__ w2,
    float* __restrict__ c0p, float* __restrict__ c1p, float* __restrict__ c2p,
    const float* __restrict__ bias)
{
    __shared__ uint32_t As[128 * AS_STRIDE];
    __shared__ uint32_t Bs[32 * BS_STRIDE];
    __shared__ float    bsh[128];

    const int z = blockIdx.z;
    const float* A  = (z == 0) ? a0p : (z == 1) ? a1p : a2p;
    const float* Wm = (z == 0) ? w0  : (z == 1) ? w1  : w2;
    float*       C  = (z == 0) ? c0p : (z == 1) ? c1p : c2p;

    const int n0 = blockIdx.x * 128;
    const int m0 = blockIdx.y * 128;

    int tid  = threadIdx.x;
    int wid  = tid >> 5;
    int lane = tid & 31;
    int grp  = lane >> 2;       // 0..7
    int tig  = lane & 3;        // 0..3
    int wm   = (wid & 1) * 64;  // warp m offset
    int wn   = (wid >> 1) * 32; // warp n offset

    if (tid < 128) bsh[tid] = bias ? bias[n0 + tid] : 0.f;

    float acc[4][4][4];
    #pragma unroll
    for (int i = 0; i < 4; i++)
        #pragma unroll
        for (int j = 0; j < 4; j++)
            #pragma unroll
            for (int r = 0; r < 4; r++) acc[i][j][r] = 0.f;

    for (int k0 = 0; k0 < 256; k0 += 32) {
        // stage A: 128 x 32, tf32-converted
        #pragma unroll
        for (int t = 0; t < 4; t++) {
            int i   = tid + t * 256;
            int row = i >> 3;
            int q   = (i & 7) * 4;
            float4 v = *(const float4*)(A + (size_t)(m0 + row) * 256 + k0 + q);
            uint4 u;
            u.x = f2tf32(v.x); u.y = f2tf32(v.y);
            u.z = f2tf32(v.z); u.w = f2tf32(v.w);
            *(uint4*)(As + row * AS_STRIDE + q) = u;
        }
        // stage B: 32 x 128 (k-major), tf32-converted
        #pragma unroll
        for (int t = 0; t < 4; t++) {
            int i = tid + t * 256;
            int k = i >> 5;
            int q = (i & 31) * 4;
            float4 v = *(const float4*)(Wm + (size_t)(k0 + k) * 256 + n0 + q);
            uint4 u;
            u.x = f2tf32(v.x); u.y = f2tf32(v.y);
            u.z = f2tf32(v.z); u.w = f2tf32(v.w);
            *(uint4*)(Bs + k * BS_STRIDE + q) = u;
        }
        __syncthreads();

        #pragma unroll
        for (int ks = 0; ks < 4; ks++) {
            int kk = ks * 8;
            uint32_t af[4][4], bf[4][2];
            #pragma unroll
            for (int mt = 0; mt < 4; mt++) {
                int r = wm + mt * 16 + grp;
                af[mt][0] = As[r * AS_STRIDE + kk + tig];
                af[mt][1] = As[(r + 8) * AS_STRIDE + kk + tig];
                af[mt][2] = As[r * AS_STRIDE + kk + tig + 4];
                af[mt][3] = As[(r + 8) * AS_STRIDE + kk + tig + 4];
            }
            #pragma unroll
            for (int nt = 0; nt < 4; nt++) {
                int c = wn + nt * 8 + grp;
                bf[nt][0] = Bs[(kk + tig) * BS_STRIDE + c];
                bf[nt][1] = Bs[(kk + tig + 4) * BS_STRIDE + c];
            }
            #pragma unroll
            for (int mt = 0; mt < 4; mt++)
                #pragma unroll
                for (int nt = 0; nt < 4; nt++)
                    asm volatile(
                        "mma.sync.aligned.m16n8k8.row.col.f32.tf32.tf32.f32 "
                        "{%0,%1,%2,%3}, {%4,%5,%6,%7}, {%8,%9}, {%0,%1,%2,%3};"
                        : "+f"(acc[mt][nt][0]), "+f"(acc[mt][nt][1]),
                          "+f"(acc[mt][nt][2]), "+f"(acc[mt][nt][3])
                        : "r"(af[mt][0]), "r"(af[mt][1]),
                          "r"(af[mt][2]), "r"(af[mt][3]),
                          "r"(bf[nt][0]), "r"(bf[nt][1]));
        }
        __syncthreads();
    }

    // epilogue
    #pragma unroll
    for (int mt = 0; mt < 4; mt++) {
        #pragma unroll
        for (int nt = 0; nt < 4; nt++) {
            int cc = wn + nt * 8 + tig * 2;
            float b0 = bsh[cc], b1 = bsh[cc + 1];
            size_t r0 = (size_t)(m0 + wm + mt * 16 + grp) * 256 + n0 + cc;
            size_t r1 = r0 + 8 * 256;
            float2 v0 = {acc[mt][nt][0] + b0, acc[mt][nt][1] + b1};
            float2 v1 = {acc[mt][nt][2] + b0, acc[mt][nt][3] + b1};
            *(float2*)(C + r0) = v0;
            *(float2*)(C + r1) = v1;
        }
    }
}

// ---------------- GCN aggregation: smem-cached gather -------------------------
// CTA = (d-quarter, batch, z). Stage xw[b][:, dq*64..+64) (512x68 floats) in
// smem, then gather edges from smem.
#define XS_STRIDE 68
#define AGG_SMEM (NN * XS_STRIDE * 4)

__global__ __launch_bounds__(256) void k_agg3(
    const float* __restrict__ xq, const float* __restrict__ xk,
    const float* __restrict__ xv,
    const float* __restrict__ bq, const float* __restrict__ bk,
    const float* __restrict__ bv,
    float* __restrict__ oq, float* __restrict__ ok_, float* __restrict__ ov)
{
    extern __shared__ float xs[];
    int dq = blockIdx.x;        // 0..3
    int b  = blockIdx.y;
    int z  = blockIdx.z;
    const float* xw   = (z == 0) ? xq : (z == 1) ? xk : xv;
    const float* bias = (z == 0) ? bq : (z == 1) ? bk : bv;
    float*       out  = (z == 0) ? oq : (z == 1) ? ok_ : ov;

    int tid = threadIdx.x;
    const float* base = xw + (size_t)b * NN * DD + dq * 64;

    #pragma unroll
    for (int t = 0; t < 32; t++) {
        int i = tid + t * 256;       // 512 rows x 16 float4
        int n = i >> 4;
        int f = (i & 15) * 4;
        *(float4*)(xs + n * XS_STRIDE + f) = *(const float4*)(base + (size_t)n * 256 + f);
    }
    __syncthreads();

    int d  = tid & 63;
    int ns = tid >> 6;               // 0..3
    float bb = bias[dq * 64 + d];
    for (int n = ns * 128; n < ns * 128 + 128; n++) {
        int s0 = g_rowptr[n], s1 = g_rowptr[n + 1];
        float acc = bb;
        for (int i = s0; i < s1; i++)
            acc += g_norm[i] * xs[g_src[i] * XS_STRIDE + d];
        out[((size_t)b * NN + n) * DD + dq * 64 + d] = acc;
    }
}

// ---------------- masked attention (full-row softmax, smem energy tile) ------
#define QT 64
#define KC 64
#define SMEM_ATTN ((QT * NN + QT * 33 + KC * 33 + QT) * 4)

__global__ __launch_bounds__(256) void k_attn(const float* __restrict__ Q,
                                              const float* __restrict__ K,
                                              const float* __restrict__ V,
                                              const int* __restrict__ mask,
                                              float* __restrict__ out) {
    extern __shared__ float sm[];
    float* Et   = sm;
    float* Qs   = Et + QT * NN;
    float* Ks   = Qs + QT * 33;
    float* lsum = Ks + KC * 33;

    int q0 = blockIdx.x * QT;
    int h  = blockIdx.y;
    int b  = blockIdx.z;
    int tid = threadIdx.x;

    const float* Qb = Q + ((size_t)b * NN + q0) * DD + h * HDIM;
    const float* Kb = K + (size_t)b * NN * DD + h * HDIM;
    const float* Vb = V + (size_t)b * NN * DD + h * HDIM;

    const float escale = 0.17677669529663687f;

    for (int idx = tid; idx < QT * HDIM; idx += 256) {
        int r = idx >> 5, d = idx & 31;
        Qs[r * 33 + d] = Qb[(size_t)r * DD + d] * escale;
    }

    int tr = tid >> 4, tc = tid & 15;

    for (int c = 0; c < NN; c += KC) {
        __syncthreads();
        for (int idx = tid; idx < KC * HDIM; idx += 256) {
            int r = idx >> 5, d = idx & 31;
            Ks[r * 33 + d] = Kb[(size_t)(c + r) * DD + d];
        }
        __syncthreads();
        float acc[4][4];
        #pragma unroll
        for (int i = 0; i < 4; i++)
            #pragma unroll
            for (int j = 0; j < 4; j++) acc[i][j] = 0.f;
        #pragma unroll
        for (int d = 0; d < HDIM; d++) {
            float qr[4], kr[4];
            #pragma unroll
            for (int i = 0; i < 4; i++) qr[i] = Qs[(tr * 4 + i) * 33 + d];
            #pragma unroll
            for (int j = 0; j < 4; j++) kr[j] = Ks[(tc * 4 + j) * 33 + d];
            #pragma unroll
            for (int i = 0; i < 4; i++)
                #pragma unroll
                for (int j = 0; j < 4; j++)
                    acc[i][j] += qr[i] * kr[j];
        }
        #pragma unroll
        for (int i = 0; i < 4; i++) {
            int qg = q0 + tr * 4 + i;
            int kg = c + tc * 4;
            int4 m4 = *(const int4*)(mask + (size_t)qg * NN + kg);
            float4 ev;
            ev.x = m4.x ? acc[i][0] : -1e10f;
            ev.y = m4.y ? acc[i][1] : -1e10f;
            ev.z = m4.z ? acc[i][2] : -1e10f;
            ev.w = m4.w ? acc[i][3] : -1e10f;
            *(float4*)(Et + (tr * 4 + i) * NN + kg) = ev;
        }
    }
    __syncthreads();

    int w = tid >> 5, lane = tid & 31;
    for (int r8 = 0; r8 < 8; r8++) {
        int r = w * 8 + r8;
        float* row = Et + r * NN;
        float m = -3.4e38f;
        #pragma unroll
        for (int t = 0; t < 16; t++) m = fmaxf(m, row[lane + 32 * t]);
        #pragma unroll
        for (int o = 16; o; o >>= 1) m = fmaxf(m, __shfl_xor_sync(0xffffffffu, m, o));
        float s = 0.f;
        #pragma unroll
        for (int t = 0; t < 16; t++) {
            float p = __expf(row[lane + 32 * t] - m);
            row[lane + 32 * t] = p;
            s += p;
        }
        #pragma unroll
        for (int o = 16; o; o >>= 1) s += __shfl_xor_sync(0xffffffffu, s, o);
        if (lane == 0) lsum[r] = s;
    }

    float oacc[8];
    #pragma unroll
    for (int q = 0; q < 8; q++) oacc[q] = 0.f;
    float* Vs = Ks;
    for (int c = 0; c < NN; c += KC) {
        __syncthreads();
        for (int idx = tid; idx < KC * HDIM; idx += 256) {
            int r = idx >> 5, d = idx & 31;
            Vs[r * 33 + d] = Vb[(size_t)(c + r) * DD + d];
        }
        __syncthreads();
        #pragma unroll 4
        for (int k = 0; k < KC; k++) {
            float v = Vs[k * 33 + lane];
            #pragma unroll
            for (int q = 0; q < 8; q++)
                oacc[q] += Et[(w * 8 + q) * NN + c + k] * v;
        }
    }

    #pragma unroll
    for (int q = 0; q < 8; q++) {
        int r = w * 8 + q;
        out[((size_t)b * NN + q0 + r) * DD + h * HDIM + lane] = oacc[q] / lsum[r];
    }
}

// ---------------- launch ------------------------------------------------------
extern "C" void kernel_launch(void* const* d_in, const int* in_sizes, int n_in,
                              void* d_out, int out_size) {
    const float* query = (const float*)d_in[0];
    const float* key   = (const float*)d_in[1];
    const float* value = (const float*)d_in[2];
    const int*   edge  = (const int*)d_in[3];
    const int*   mask  = (const int*)d_in[4];
    const float* Wq = (const float*)d_in[5];
    const float* bq = (const float*)d_in[6];
    const float* Wk = (const float*)d_in[7];
    const float* bk = (const float*)d_in[8];
    const float* Wv = (const float*)d_in[9];
    const float* bv = (const float*)d_in[10];
    const float* Wo = (const float*)d_in[11];
    const float* bo = (const float*)d_in[12];
    float* out = (float*)d_out;

    float *xwq, *xwk, *xwv, *Qp, *Kp, *Vp, *att;
    cudaGetSymbolAddress((void**)&xwq, g_xwq);
    cudaGetSymbolAddress((void**)&xwk, g_xwk);
    cudaGetSymbolAddress((void**)&xwv, g_xwv);
    cudaGetSymbolAddress((void**)&Qp,  g_Q);
    cudaGetSymbolAddress((void**)&Kp,  g_K);
    cudaGetSymbolAddress((void**)&Vp,  g_V);
    cudaGetSymbolAddress((void**)&att, g_att);

    cudaFuncSetAttribute(k_attn, cudaFuncAttributeMaxDynamicSharedMemorySize,
                         SMEM_ATTN);
    cudaFuncSetAttribute(k_agg3, cudaFuncAttributeMaxDynamicSharedMemorySize,
                         AGG_SMEM);

    // graph prep
    k_detect<<<1, 1>>>(edge);
    k_init<<<1, NN>>>();
    k_deg <<<(ETOT + 255) / 256, 256>>>(edge);
    k_scan<<<1, NN>>>();
    k_fill<<<(ETOT + 255) / 256, 256>>>(edge);

    // fused QKV projection (tf32 tensor cores)
    k_gemm_mma<<<dim3(2, 128, 3), 256>>>(query, key, value,
                                         Wq, Wk, Wv,
                                         xwq, xwk, xwv, nullptr);
    // fused GCN aggregation (+bias), smem-cached gather
    k_agg3<<<dim3(4, BB, 3), 256, AGG_SMEM>>>(xwq, xwk, xwv,
                                              bq, bk, bv, Qp, Kp, Vp);

    // masked multi-head attention
    k_attn<<<dim3(NN / QT, HH, BB), 256, SMEM_ATTN>>>(Qp, Kp, Vp, mask, att);

    // output projection (+bias) straight into d_out
    k_gemm_mma<<<dim3(2, 128, 1), 256>>>(att, att, att,
                                         Wo, Wo, Wo,
                                         out, out, out, bo);
}